// round 16
// baseline (speedup 1.0000x reference)
#include <cuda_runtime.h>
#include <math.h>

// Problem constants
#define B_  32
#define T_  32
#define I_  256
#define H_  512
#define NH_ 4
#define HS_ 64
#define MS_ 2048
#define O_  256
// derived
#define KG_ 1024
#define NG_ 2048        // 4*H; gate col index n' = j*4 + g  (gate-interleaved)
#define NHP_ 516
#define HPROW_ 2115
#define NBLK 256
#define NTHR 256

typedef unsigned long long u64;

__device__ __forceinline__ u64 ffma2(u64 a, u64 b, u64 c) {
    u64 d; asm("fma.rn.f32x2 %0, %1, %2, %3;" : "=l"(d) : "l"(a), "l"(b), "l"(c)); return d;
}
__device__ __forceinline__ u64 fadd2(u64 a, u64 b) {
    u64 d; asm("add.rn.f32x2 %0, %1, %2;" : "=l"(d) : "l"(a), "l"(b)); return d;
}
__device__ __forceinline__ u64 pack2(float lo, float hi) {
    u64 d; asm("mov.b64 %0, {%1, %2};" : "=l"(d) : "f"(lo), "f"(hi)); return d;
}
__device__ __forceinline__ float2 unpack2(u64 v) {
    float2 r; asm("mov.b64 {%0, %1}, %2;" : "=f"(r.x), "=f"(r.y) : "l"(v)); return r;
}

// ---------------- scratch (device globals; no allocation allowed) ----------------
__device__ float g_WgT[KG_*NG_];              // [k][n']  n' = j*4+g   8MB
__device__ float g_WhT[H_*NHP_];              // [k][n*129+p]
__device__ float g_WoT[(H_+NH_*HS_)*O_];      // [k][o]
__device__ float g_h[B_*H_];
__device__ float g_c[B_*H_];
__device__ float g_gates_part[16][B_][NG_];   // k-split (16 slices of 64) partial gates (n')
__device__ float g_hp_part[16][B_][NHP_];
__device__ float2 g_stats[B_][8][8];          // [b][key][mq] = {chunk max, chunk sumexp}
__device__ float g_read_part[T_][8][B_][NH_*HS_];
__device__ float g_hist_h[T_][B_][H_];
__device__ float g_mem[B_][MS_][HS_];         // 16.7MB
__device__ int   g_bar[T_];                   // global barrier (1 per step)
__device__ int   g_barG[T_][64];              // [0..15] P1->P2 (bid>>4), [16..31] P2->P3 (bid&15), [32..63] P3->P4 (ab)

// fast transcendentals (approx exp/div; errors ~1e-7, contractive in LSTM)
__device__ __forceinline__ float sigm_f(float v) {
    return __fdividef(1.f, 1.f + __expf(-v));
}
__device__ __forceinline__ float tanh_f(float v) {
    float e = __expf(-2.f * v);
    return __fdividef(1.f - e, 1.f + e);
}

// ---------------- barriers: release-add + acquire-poll, no L1 flush ----------------
__device__ __forceinline__ void barwait(int* p, int cnt) {
    __syncthreads();
    if (threadIdx.x == 0) {
        asm volatile("red.release.gpu.global.add.s32 [%0], 1;" :: "l"(p) : "memory");
        int v;
        do {
            asm volatile("ld.acquire.gpu.global.s32 %0, [%1];" : "=r"(v) : "l"(p) : "memory");
        } while (v < cnt);
    }
    __syncthreads();
}

// ---------------- fused prep: transposes + zeroing in ONE launch ----------------
__global__ void k_prep(const float* __restrict__ W_ih, const float* __restrict__ W_hh,
                       const float* __restrict__ W_head, const float* __restrict__ W_out) {
    const int b = blockIdx.x;
    const int tid = threadIdx.x;                // 256
    const int tx = tid & 31, ty = tid >> 5;     // (32, 8)
    __shared__ float tile[32][33];
    if (b < 2048) {                             // WgT[k][n'] = W[row(n')][k], row = (n'&3)*512 + (n'>>2)
        int bx = (b & 31) * 32, by = (b >> 5) * 32;
        #pragma unroll
        for (int i = 0; i < 32; i += 8) {
            int np = by + ty + i, k = bx + tx;
            int row = (np & 3) * 512 + (np >> 2);
            tile[ty + i][tx] = (k < 512) ? W_ih[row*512 + k] : W_hh[row*512 + (k - 512)];
        }
        __syncthreads();
        #pragma unroll
        for (int i = 0; i < 32; i += 8) {
            int k = bx + ty + i, np = by + tx;
            g_WgT[(size_t)k * NG_ + np] = tile[tx][ty + i];
        }
    } else if (b < 2048 + 272) {                // WhT[k][r]
        int bb = b - 2048;
        int bx = (bb & 15) * 32, by = (bb >> 4) * 32;
        #pragma unroll
        for (int i = 0; i < 32; i += 8) {
            int r = by + ty + i, k = bx + tx;
            float v = 0.f;
            if (r < NHP_) {
                int n = r / 129, p = r % 129;
                v = W_head[(size_t)(n * HPROW_ + p) * 512 + k];
            }
            tile[ty + i][tx] = v;
        }
        __syncthreads();
        #pragma unroll
        for (int i = 0; i < 32; i += 8) {
            int k = bx + ty + i, r = by + tx;
            if (r < NHP_) g_WhT[(size_t)k * NHP_ + r] = tile[tx][ty + i];
        }
    } else if (b < 2048 + 272 + 192) {          // WoT[k][o]
        int bb = b - 2320;
        int bx = (bb % 24) * 32, by = (bb / 24) * 32;
        #pragma unroll
        for (int i = 0; i < 32; i += 8) {
            int o = by + ty + i, k = bx + tx;
            tile[ty + i][tx] = W_out[o * (H_ + NH_*HS_) + k];
        }
        __syncthreads();
        #pragma unroll
        for (int i = 0; i < 32; i += 8) {
            int k = bx + ty + i, o = by + tx;
            g_WoT[(size_t)k * O_ + o] = tile[tx][ty + i];
        }
    } else {
        int bb = b - 2512;                      // 0..511
        int gtid = bb * 256 + tid;
        float4 z4 = make_float4(0.f, 0.f, 0.f, 0.f);
        #pragma unroll
        for (int i = 0; i < 8; ++i)
            ((float4*)g_mem)[gtid + i * 131072] = z4;
        if (gtid < 4096)                  ((float4*)g_h)[gtid] = z4;
        else if (gtid < 8192)             ((float4*)g_c)[gtid - 4096] = z4;
        else if (gtid < 8192 + T_)        g_bar[gtid - 8192] = 0;
        else if (gtid < 8192 + T_ + T_*64)
            (&g_barG[0][0])[gtid - 8192 - T_] = 0;
    }
}

__global__ void k_nop() {}

// ---------------- the persistent recurrence kernel (256 blocks x 256 threads, 2/SM) --------
struct SmGates { u64 vp[64][18]; };      // {v(2p), v(2p+1)} pairs
struct SmP2    { float h[2][32]; };
struct SmAttn  {
    float key[8][64];
    float sc[8][260];                    // raw scores -> exp(s - gm_chunk) in place
    float gm[8], inv[8], ws[4];
    float sk[4][64];
    float racc[8][4][64];
};
union __align__(16) SmU { SmGates g; SmP2 p2; SmAttn a; };

__global__ __launch_bounds__(NTHR, 2)
void k_steps(const float* __restrict__ x, const float* __restrict__ b_ih,
             const float* __restrict__ b_hh, const float* __restrict__ b_head) {
    __shared__ SmU sm;
    const int bid = blockIdx.x, tid = threadIdx.x;
    const int wrp = tid >> 5, lane = tid & 31;

    // P1 partition: (16 j-chunks of 128 n'-cols) x (16 k-slices of 64)
    const int jc = bid >> 4, ksl = bid & 15;
    const int n0 = jc * 128, k0g = ksl * 64;
    const int c_l = lane & 7, bgrp = lane >> 3;      // 8 col-subs x 4 batch-groups
    const int col0 = n0 + wrp * 16 + c_l * 2;        // warp = colgrp (n'-index)
    // P2 partition: (16 j-slices of 32) x (16 batch-pairs)  [group-aligned with P1]
    const int ks2 = bid >> 4, bq2 = bid & 15;
    const int b02 = bq2 * 2, j0 = ks2 * 32;
    // P3/P4 partition: ab = ((bid&15)<<1)|(bid>>7); mq = (bid>>4)&7  [group-aligned with P2]
    const int ab = ((bid & 15) << 1) | (bid >> 7);
    const int mq = (bid >> 4) & 7;
    const int m0 = mq * 256;
    const int hq = lane & 7, msub = lane >> 3;

    for (int t = 0; t < T_; ++t) {
        // ================= P1: gates GEMM (16 k-slice partials, gate-interleaved cols) =====
        {
            // build v pair tile vp[k][p] = {v(2p), v(2p+1)} : 64k x 16 pairs
            #pragma unroll
            for (int e = 0; e < 4; ++e) {
                int idx = e * 256 + tid;
                int kk = idx & 63, p = idx >> 6;
                int gk = k0g + kk;
                int bb = p * 2;
                float v0, v1;
                if (gk < 256) {
                    v0 = __ldg(&x[(bb * T_ + t) * I_ + gk]);
                    v1 = __ldg(&x[((bb+1) * T_ + t) * I_ + gk]);
                } else if (gk < 512) {
                    if (t == 0) { v0 = 0.f; v1 = 0.f; }
                    else {
                        int r = gk - 256;
                        v0 = 0.f; v1 = 0.f;
                        #pragma unroll
                        for (int mc = 0; mc < 8; ++mc) {
                            v0 += __ldcg(&g_read_part[t-1][mc][bb][r]);
                            v1 += __ldcg(&g_read_part[t-1][mc][bb+1][r]);
                        }
                    }
                } else {
                    v0 = __ldcg(&g_h[bb * H_ + (gk - 512)]);
                    v1 = __ldcg(&g_h[(bb+1) * H_ + (gk - 512)]);
                }
                sm.g.vp[kk][p] = pack2(v0, v1);
            }
            __syncthreads();
            u64 acc[2][4];
            {
                u64 b0p = 0ull, b1p = 0ull;
                if (ksl == 0) {
                    int r0 = (col0 & 3) * 512 + (col0 >> 2);
                    int r1 = ((col0+1) & 3) * 512 + ((col0+1) >> 2);
                    float bi0 = __ldg(&b_ih[r0]) + __ldg(&b_hh[r0]);
                    float bi1 = __ldg(&b_ih[r1]) + __ldg(&b_hh[r1]);
                    b0p = pack2(bi0, bi0); b1p = pack2(bi1, bi1);
                }
                #pragma unroll
                for (int p = 0; p < 4; ++p) { acc[0][p] = b0p; acc[1][p] = b1p; }
            }
            const float2* wp2 = (const float2*)&g_WgT[(size_t)k0g * NG_ + col0];
            const int p0 = bgrp * 4;
            #pragma unroll 8
            for (int kk = 0; kk < 64; ++kk) {
                float2 w = __ldg(wp2 + (size_t)kk * (NG_/2));
                u64 w20 = pack2(w.x, w.x);
                u64 w21 = pack2(w.y, w.y);
                ulonglong2 va = *(const ulonglong2*)&sm.g.vp[kk][p0];
                ulonglong2 vb = *(const ulonglong2*)&sm.g.vp[kk][p0 + 2];
                acc[0][0] = ffma2(va.x, w20, acc[0][0]);
                acc[0][1] = ffma2(va.y, w20, acc[0][1]);
                acc[0][2] = ffma2(vb.x, w20, acc[0][2]);
                acc[0][3] = ffma2(vb.y, w20, acc[0][3]);
                acc[1][0] = ffma2(va.x, w21, acc[1][0]);
                acc[1][1] = ffma2(va.y, w21, acc[1][1]);
                acc[1][2] = ffma2(vb.x, w21, acc[1][2]);
                acc[1][3] = ffma2(vb.y, w21, acc[1][3]);
            }
            #pragma unroll
            for (int p = 0; p < 4; ++p) {
                float2 c0 = unpack2(acc[0][p]);
                float2 c1 = unpack2(acc[1][p]);
                int b = bgrp * 8 + p * 2;
                *(float2*)&g_gates_part[ksl][b][col0]     = make_float2(c0.x, c1.x);
                *(float2*)&g_gates_part[ksl][b + 1][col0] = make_float2(c0.y, c1.y);
            }
            __syncthreads();
        }
        barwait(&g_barG[t][bid >> 4], 16);      // 16-group: P1 -> P2 (gates j-slice local)

        // ================= P2: LSTM (quad-spread, vectorized gates) + head GEMM ============
        {
            {
                const int cell = tid >> 2, q = tid & 3;     // 64 cells: 2 b x 32 j
                const int bi = cell >> 5, jj = cell & 31;
                const int b = b02 + bi, j = j0 + jj;
                float4 gs = make_float4(0.f, 0.f, 0.f, 0.f);
                #pragma unroll
                for (int e = 0; e < 4; ++e) {
                    int s = q * 4 + e;
                    float4 ga = __ldcg((const float4*)&g_gates_part[s][b][j * 4]);
                    gs.x += ga.x; gs.y += ga.y; gs.z += ga.z; gs.w += ga.w;
                }
                gs.x += __shfl_xor_sync(0xffffffffu, gs.x, 1);
                gs.y += __shfl_xor_sync(0xffffffffu, gs.y, 1);
                gs.z += __shfl_xor_sync(0xffffffffu, gs.z, 1);
                gs.w += __shfl_xor_sync(0xffffffffu, gs.w, 1);
                gs.x += __shfl_xor_sync(0xffffffffu, gs.x, 2);
                gs.y += __shfl_xor_sync(0xffffffffu, gs.y, 2);
                gs.z += __shfl_xor_sync(0xffffffffu, gs.z, 2);
                gs.w += __shfl_xor_sync(0xffffffffu, gs.w, 2);
                if (q == 0) {
                    float cold = g_c[b * H_ + j];
                    float iv = sigm_f(gs.x), fv = sigm_f(gs.y);
                    float gv = tanh_f(gs.z), ov = sigm_f(gs.w);
                    float cn = fv * cold + iv * gv;
                    float hn = ov * tanh_f(cn);
                    g_c[b * H_ + j] = cn;
                    g_h[b * H_ + j] = hn;
                    g_hist_h[t][b][j] = hn;
                    sm.p2.h[bi][jj] = hn;
                }
            }
            __syncthreads();
            #pragma unroll
            for (int e = 0; e < 3; ++e) {
                int nn = tid + e * 256;
                if (nn < NHP_) {
                    float a0 = 0.f, a1 = 0.f;
                    #pragma unroll
                    for (int k = 0; k < 32; ++k) {
                        float w = __ldcg(&g_WhT[(size_t)(j0 + k) * NHP_ + nn]);
                        a0 += sm.p2.h[0][k] * w;
                        a1 += sm.p2.h[1][k] * w;
                    }
                    g_hp_part[ks2][b02 + 0][nn] = a0;
                    g_hp_part[ks2][b02 + 1][nn] = a1;
                }
            }
        }
        // hoist block-private mem-row loads above the barrier (coalesced)
        ulonglong2 rows2[8][2];
        #pragma unroll
        for (int it = 0; it < 8; ++it) {
            const float* mp = &g_mem[ab][m0 + it*32 + wrp*4 + msub][0];
            rows2[it][0] = *(const ulonglong2*)(mp + hq * 4);
            rows2[it][1] = *(const ulonglong2*)(mp + 32 + hq * 4);
        }
        barwait(&g_barG[t][16 + (bid & 15)], 16);   // strided 16-group: P2 -> P3 (hp_part)

        // ================= P3: keys + ws + scores + sk + chunk stats =================
        {
            #pragma unroll
            for (int e = 0; e < 2; ++e) {       // key build: 512 entries, 2 per thread
                int idx = e * 256 + tid;
                int key = idx >> 6, h = idx & 63;
                int n = key & 3;
                int p = (key < 4) ? h : 64 + h;
                float v = __ldg(&b_head[n * HPROW_ + p]);
                #pragma unroll
                for (int ps = 0; ps < 16; ++ps) v += __ldcg(&g_hp_part[ps][ab][n * 129 + p]);
                sm.a.key[key][h] = v * 0.125f;
            }
            if (tid < 4) {
                int nw = tid;
                float vw = __ldg(&b_head[nw * HPROW_ + 128]);
                #pragma unroll
                for (int ps = 0; ps < 16; ++ps) vw += __ldcg(&g_hp_part[ps][ab][nw * 129 + 128]);
                sm.a.ws[nw] = sigm_f(vw);
            }
            __syncthreads();
            // scores: 2 passes of 4 keys, keys register-hoisted out of the it-loop
            #pragma unroll
            for (int kp = 0; kp < 2; ++kp) {
                const int kb = kp * 4;
                ulonglong2 klo[4], khi[4];
                #pragma unroll
                for (int kq = 0; kq < 4; ++kq) {
                    klo[kq] = *(const ulonglong2*)&sm.a.key[kb + kq][hq * 4];
                    khi[kq] = *(const ulonglong2*)&sm.a.key[kb + kq][32 + hq * 4];
                }
                #pragma unroll
                for (int it = 0; it < 8; ++it) {
                    float pv[4];
                    #pragma unroll
                    for (int kq = 0; kq < 4; ++kq) {
                        u64 d2 = ffma2(rows2[it][0].x, klo[kq].x, 0ull);
                        d2 = ffma2(rows2[it][0].y, klo[kq].y, d2);
                        d2 = ffma2(rows2[it][1].x, khi[kq].x, d2);
                        d2 = ffma2(rows2[it][1].y, khi[kq].y, d2);
                        float2 pf = unpack2(d2);
                        pv[kq] = pf.x + pf.y;
                    }
                    // butterfly over hq: xor1/xor2 key-splits, xor4 plain add
                    float q2v[2];
                    #pragma unroll
                    for (int k2 = 0; k2 < 2; ++k2) {
                        float send = (hq & 1) ? pv[2*k2] : pv[2*k2+1];
                        float recv = __shfl_xor_sync(0xffffffffu, send, 1);
                        float keepv = (hq & 1) ? pv[2*k2+1] : pv[2*k2];
                        q2v[k2] = keepv + recv;
                    }
                    float r1;
                    {
                        float send = (hq & 2) ? q2v[0] : q2v[1];
                        float recv = __shfl_xor_sync(0xffffffffu, send, 2);
                        float keepv = (hq & 2) ? q2v[1] : q2v[0];
                        r1 = keepv + recv;
                    }
                    r1 += __shfl_xor_sync(0xffffffffu, r1, 4);
                    if (hq < 4) sm.a.sc[kb + hq][it*32 + wrp*4 + msub] = r1;
                }
            }
            // sk build (needs ws + hp_part; independent of sc stats below)
            {
                int n = tid >> 6, h = tid & 63;
                float v = __ldg(&b_head[n * HPROW_ + 64 + h]);
                #pragma unroll
                for (int ps = 0; ps < 16; ++ps) v += __ldcg(&g_hp_part[ps][ab][n * 129 + 64 + h]);
                sm.a.sk[n][h] = v * sm.a.ws[n];
            }
            __syncthreads();
            if (wrp < 8) {      // chunk max per key (8 warps = 8 keys)
                float mx = -1e30f;
                for (int i = lane; i < 256; i += 32) mx = fmaxf(mx, sm.a.sc[wrp][i]);
                #pragma unroll
                for (int sh = 16; sh; sh >>= 1) mx = fmaxf(mx, __shfl_xor_sync(0xffffffffu, mx, sh));
                if (lane == 0) sm.a.gm[wrp] = mx;
            }
            __syncthreads();
            #pragma unroll
            for (int key = 0; key < 8; ++key)     // exp in place
                sm.a.sc[key][tid] = __expf(sm.a.sc[key][tid] - sm.a.gm[key]);
            __syncthreads();
            if (wrp < 8) {      // chunk sumexp
                float se = 0.f;
                for (int i = lane; i < 256; i += 32) se += sm.a.sc[wrp][i];
                #pragma unroll
                for (int sh = 16; sh; sh >>= 1) se += __shfl_xor_sync(0xffffffffu, se, sh);
                if (lane == 0) g_stats[ab][wrp][mq] = make_float2(sm.a.gm[wrp], se);
            }
        }
        barwait(&g_barG[t][32 + ab], 8);        // 8-group: P3 -> P4 (stats per-ab)

        // ================= P4: softmax apply on register rows, read acc, mem update ==========
        {
            if (tid < 8) {
                float gm = -1e30f;
                float2 st[8];
                #pragma unroll
                for (int c = 0; c < 8; ++c) {
                    st[c] = __ldcg(&g_stats[ab][tid][c]);
                    gm = fmaxf(gm, st[c].x);
                }
                float ssum = 0.f;
                #pragma unroll
                for (int c = 0; c < 8; ++c) ssum += st[c].y * __expf(st[c].x - gm);
                sm.a.inv[tid] = __expf(sm.a.gm[tid] - gm) / ssum;
            }
            __syncthreads();
            float scl[8];
            #pragma unroll
            for (int key = 0; key < 8; ++key) scl[key] = sm.a.inv[key];

            u64 racc2[4][4];
            #pragma unroll
            for (int n = 0; n < 4; ++n)
                #pragma unroll
                for (int q2 = 0; q2 < 4; ++q2) racc2[n][q2] = 0ull;

            #pragma unroll
            for (int it = 0; it < 8; ++it) {
                const int ml = it*32 + wrp*4 + msub;
                float wv[8];
                #pragma unroll
                for (int n = 0; n < 8; ++n) wv[n] = sm.a.sc[n][ml] * scl[n];
                ulonglong2 rlo = rows2[it][0], rhi = rows2[it][1];
                #pragma unroll
                for (int n = 0; n < 4; ++n) {
                    u64 rw2 = pack2(wv[n], wv[n]);
                    racc2[n][0] = ffma2(rw2, rlo.x, racc2[n][0]);
                    racc2[n][1] = ffma2(rw2, rlo.y, racc2[n][1]);
                    racc2[n][2] = ffma2(rw2, rhi.x, racc2[n][2]);
                    racc2[n][3] = ffma2(rw2, rhi.y, racc2[n][3]);
                }
                #pragma unroll
                for (int n = 0; n < 4; ++n) {
                    u64 ww2 = pack2(wv[4 + n], wv[4 + n]);
                    ulonglong2 slo = *(const ulonglong2*)&sm.a.sk[n][hq * 4];
                    ulonglong2 shi = *(const ulonglong2*)&sm.a.sk[n][32 + hq * 4];
                    rlo.x = ffma2(ww2, slo.x, rlo.x);
                    rlo.y = ffma2(ww2, slo.y, rlo.y);
                    rhi.x = ffma2(ww2, shi.x, rhi.x);
                    rhi.y = ffma2(ww2, shi.y, rhi.y);
                }
                float* mp = &g_mem[ab][m0 + ml][0];
                *(ulonglong2*)(mp + hq * 4) = rlo;
                *(ulonglong2*)(mp + 32 + hq * 4) = rhi;
            }
            // reduce read partials over msub (xor 8, 16)
            #pragma unroll
            for (int n = 0; n < 4; ++n)
                #pragma unroll
                for (int q2 = 0; q2 < 4; ++q2) {
                    racc2[n][q2] = fadd2(racc2[n][q2], __shfl_xor_sync(0xffffffffu, racc2[n][q2], 8));
                    racc2[n][q2] = fadd2(racc2[n][q2], __shfl_xor_sync(0xffffffffu, racc2[n][q2], 16));
                }
            if (lane < 8) {   // msub == 0, hq == lane
                #pragma unroll
                for (int n = 0; n < 4; ++n) {
                    float2 p0 = unpack2(racc2[n][0]);
                    float2 p1 = unpack2(racc2[n][1]);
                    float2 p2 = unpack2(racc2[n][2]);
                    float2 p3 = unpack2(racc2[n][3]);
                    *(float2*)&sm.a.racc[wrp][n][hq*4]          = p0;
                    *(float2*)&sm.a.racc[wrp][n][hq*4 + 2]      = p1;
                    *(float2*)&sm.a.racc[wrp][n][32 + hq*4]     = p2;
                    *(float2*)&sm.a.racc[wrp][n][32 + hq*4 + 2] = p3;
                }
            }
            __syncthreads();
            {
                int n = tid >> 6, h = tid & 63;
                float ssum = 0.f;
                #pragma unroll
                for (int wr = 0; wr < 8; ++wr) ssum += sm.a.racc[wr][n][h];
                g_read_part[t][mq][ab][n * 64 + h] = ssum;
            }
        }
        barwait(&g_bar[t], NBLK);               // global: P4 -> next P1
    }
}

// ---------------- final output GEMM: outputs[b][t][o] ----------------
__global__ void k_out(const float* __restrict__ b_out, float* __restrict__ out) {
    const int m0 = blockIdx.x * 32, nc = blockIdx.y;
    const int tid = threadIdx.x;
    __shared__ float a_sh[32][64];
    const int n_l = tid & 63, mg = tid >> 6;
    const int n = nc * 64 + n_l;
    float acc[8];
    #pragma unroll
    for (int r = 0; r < 8; ++r) acc[r] = 0.f;
    for (int kt = 0; kt < 12; ++kt) {
        __syncthreads();
        #pragma unroll
        for (int e = 0; e < 8; ++e) {
            int lidx = e * 256 + tid;
            int mrow = lidx >> 6, kk = lidx & 63;
            int m = m0 + mrow;
            int ts = m >> 5, bb = m & 31;
            int gk = kt * 64 + kk;
            float v;
            if (gk < 512) v = g_hist_h[ts][bb][gk];
            else {
                int r = gk - 512;
                v = 0.f;
                #pragma unroll
                for (int mc = 0; mc < 8; ++mc) v += g_read_part[ts][mc][bb][r];
            }
            a_sh[mrow][kk] = v;
        }
        __syncthreads();
        #pragma unroll 4
        for (int kk = 0; kk < 64; ++kk) {
            float wv = g_WoT[(kt * 64 + kk) * O_ + n];
            #pragma unroll
            for (int r = 0; r < 8; ++r) acc[r] += a_sh[mg * 8 + r][kk] * wv;
        }
    }
    float bo = b_out[n];
    #pragma unroll
    for (int r = 0; r < 8; ++r) {
        int m = m0 + mg * 8 + r;
        int ts = m >> 5, bb = m & 31;
        out[(bb * T_ + ts) * O_ + n] = acc[r] + bo;
    }
}

// ---------------- final state copy: mem, h, c into d_out ----------------
__global__ void k_final(float* __restrict__ out) {
    const int OUT_N = B_ * T_ * O_;
    const int NMEM  = B_ * MS_ * HS_;
    const int total = NMEM + 2 * B_ * H_;
    for (int i = blockIdx.x * blockDim.x + threadIdx.x; i < total; i += gridDim.x * blockDim.x) {
        if (i < NMEM)                 out[OUT_N + i] = (&g_mem[0][0][0])[i];
        else if (i < NMEM + B_ * H_)  out[OUT_N + i] = g_h[i - NMEM];
        else                          out[OUT_N + i] = g_c[i - NMEM - B_ * H_];
    }
}

extern "C" void kernel_launch(void* const* d_in, const int* in_sizes, int n_in,
                              void* d_out, int out_size) {
    const float* x      = (const float*)d_in[0];
    const float* W_ih   = (const float*)d_in[1];
    const float* W_hh   = (const float*)d_in[2];
    const float* b_ih   = (const float*)d_in[3];
    const float* b_hh   = (const float*)d_in[4];
    const float* W_head = (const float*)d_in[5];
    const float* b_head = (const float*)d_in[6];
    const float* W_out  = (const float*)d_in[7];
    const float* b_out  = (const float*)d_in[8];
    float* out = (float*)d_out;

    k_prep<<<3024, 256>>>(W_ih, W_hh, W_head, W_out);
    k_nop<<<1, 32>>>();
    k_nop<<<1, 32>>>();
    k_steps<<<NBLK, NTHR>>>(x, b_ih, b_hh, b_head);
    k_out<<<dim3(32, 4), 256>>>(b_out, out);
    k_final<<<2048, 256>>>(out);
}

// round 17
// speedup vs baseline: 1.0063x; 1.0063x over previous
#include <cuda_runtime.h>
#include <math.h>

// Problem constants
#define B_  32
#define T_  32
#define I_  256
#define H_  512
#define NH_ 4
#define HS_ 64
#define MS_ 2048
#define O_  256
// derived
#define KG_ 1024
#define NG_ 2048        // 4*H; gate col index n' = j*4 + g  (gate-interleaved)
#define NHP_ 516
#define HPROW_ 2115
#define NBLK 256
#define NTHR 256
#define NBARG (2*T_)    // global barriers (2 per step)

typedef unsigned long long u64;

__device__ __forceinline__ u64 ffma2(u64 a, u64 b, u64 c) {
    u64 d; asm("fma.rn.f32x2 %0, %1, %2, %3;" : "=l"(d) : "l"(a), "l"(b), "l"(c)); return d;
}
__device__ __forceinline__ u64 fadd2(u64 a, u64 b) {
    u64 d; asm("add.rn.f32x2 %0, %1, %2;" : "=l"(d) : "l"(a), "l"(b)); return d;
}
__device__ __forceinline__ u64 pack2(float lo, float hi) {
    u64 d; asm("mov.b64 %0, {%1, %2};" : "=l"(d) : "f"(lo), "f"(hi)); return d;
}
__device__ __forceinline__ float2 unpack2(u64 v) {
    float2 r; asm("mov.b64 {%0, %1}, %2;" : "=f"(r.x), "=f"(r.y) : "l"(v)); return r;
}

// ---------------- scratch (device globals; no allocation allowed) ----------------
__device__ float g_WgT[KG_*NG_];              // [k][n']  n' = j*4+g   8MB
__device__ float g_WhT[H_*NHP_];              // [k][n*129+p]
__device__ float g_WoT[(H_+NH_*HS_)*O_];      // [k][o]
__device__ float g_h[B_*H_];
__device__ float g_c[B_*H_];
__device__ float g_gates_part[16][B_][NG_];   // k-split (16 slices of 64) partial gates (n')
__device__ float g_hp_part[16][B_][NHP_];
__device__ float2 g_stats[B_][8][8];          // [b][key][mq] = {chunk max, chunk sumexp}
__device__ float g_read_part[T_][8][B_][NH_*HS_];
__device__ float g_hist_h[T_][B_][H_];
__device__ float g_mem[B_][MS_][HS_];         // 16.7MB
__device__ int   g_bar[NBARG];                // global barrier counters
__device__ int   g_barG[T_][48];              // per-step: [0..15]=16-groups, [16..47]=8-groups

// fast transcendentals (approx exp/div; errors ~1e-7, contractive in LSTM)
__device__ __forceinline__ float sigm_f(float v) {
    return __fdividef(1.f, 1.f + __expf(-v));
}
__device__ __forceinline__ float tanh_f(float v) {
    float e = __expf(-2.f * v);
    return __fdividef(1.f - e, 1.f + e);
}

// ---------------- barriers: release-add + acquire-poll, no L1 flush ----------------
__device__ __forceinline__ void barwait(int* p, int cnt) {
    __syncthreads();
    if (threadIdx.x == 0) {
        asm volatile("red.release.gpu.global.add.s32 [%0], 1;" :: "l"(p) : "memory");
        int v;
        do {
            asm volatile("ld.acquire.gpu.global.s32 %0, [%1];" : "=r"(v) : "l"(p) : "memory");
        } while (v < cnt);
    }
    __syncthreads();
}

// ---------------- fused prep: transposes + zeroing in ONE launch ----------------
__global__ void k_prep(const float* __restrict__ W_ih, const float* __restrict__ W_hh,
                       const float* __restrict__ W_head, const float* __restrict__ W_out) {
    const int b = blockIdx.x;
    const int tid = threadIdx.x;                // 256
    const int tx = tid & 31, ty = tid >> 5;     // (32, 8)
    __shared__ float tile[32][33];
    if (b < 2048) {                             // WgT[k][n'] = W[row(n')][k], row = (n'&3)*512 + (n'>>2)
        int bx = (b & 31) * 32, by = (b >> 5) * 32;
        #pragma unroll
        for (int i = 0; i < 32; i += 8) {
            int np = by + ty + i, k = bx + tx;
            int row = (np & 3) * 512 + (np >> 2);
            tile[ty + i][tx] = (k < 512) ? W_ih[row*512 + k] : W_hh[row*512 + (k - 512)];
        }
        __syncthreads();
        #pragma unroll
        for (int i = 0; i < 32; i += 8) {
            int k = bx + ty + i, np = by + tx;
            g_WgT[(size_t)k * NG_ + np] = tile[tx][ty + i];
        }
    } else if (b < 2048 + 272) {                // WhT[k][r]
        int bb = b - 2048;
        int bx = (bb & 15) * 32, by = (bb >> 4) * 32;
        #pragma unroll
        for (int i = 0; i < 32; i += 8) {
            int r = by + ty + i, k = bx + tx;
            float v = 0.f;
            if (r < NHP_) {
                int n = r / 129, p = r % 129;
                v = W_head[(size_t)(n * HPROW_ + p) * 512 + k];
            }
            tile[ty + i][tx] = v;
        }
        __syncthreads();
        #pragma unroll
        for (int i = 0; i < 32; i += 8) {
            int k = bx + ty + i, r = by + tx;
            if (r < NHP_) g_WhT[(size_t)k * NHP_ + r] = tile[tx][ty + i];
        }
    } else if (b < 2048 + 272 + 192) {          // WoT[k][o]
        int bb = b - 2320;
        int bx = (bb % 24) * 32, by = (bb / 24) * 32;
        #pragma unroll
        for (int i = 0; i < 32; i += 8) {
            int o = by + ty + i, k = bx + tx;
            tile[ty + i][tx] = W_out[o * (H_ + NH_*HS_) + k];
        }
        __syncthreads();
        #pragma unroll
        for (int i = 0; i < 32; i += 8) {
            int k = bx + ty + i, o = by + tx;
            g_WoT[(size_t)k * O_ + o] = tile[tx][ty + i];
        }
    } else {
        int bb = b - 2512;                      // 0..511
        int gtid = bb * 256 + tid;
        float4 z4 = make_float4(0.f, 0.f, 0.f, 0.f);
        #pragma unroll
        for (int i = 0; i < 8; ++i)
            ((float4*)g_mem)[gtid + i * 131072] = z4;
        if (gtid < 4096)                  ((float4*)g_h)[gtid] = z4;
        else if (gtid < 8192)             ((float4*)g_c)[gtid - 4096] = z4;
        else if (gtid < 8192 + NBARG)     g_bar[gtid - 8192] = 0;
        else if (gtid < 8192 + NBARG + T_*48)
            (&g_barG[0][0])[gtid - 8192 - NBARG] = 0;
    }
}

__global__ void k_nop() {}

// ---------------- the persistent recurrence kernel (256 blocks x 256 threads, 2/SM) --------
struct SmGates { u64 vp[64][18]; };      // {v(2p), v(2p+1)} pairs
struct SmP2    { float h[2][32]; };
struct SmAttn  {
    float key[8][64];
    float sc[8][260];                    // raw scores -> exp(s - gm_chunk) in place
    float gm[8], inv[8], ws[4];
    float sk[4][64];
    float racc[8][4][64];
};
union __align__(16) SmU { SmGates g; SmP2 p2; SmAttn a; };

__global__ __launch_bounds__(NTHR, 2)
void k_steps(const float* __restrict__ x, const float* __restrict__ b_ih,
             const float* __restrict__ b_hh, const float* __restrict__ b_head) {
    __shared__ SmU sm;
    const int bid = blockIdx.x, tid = threadIdx.x;
    const int wrp = tid >> 5, lane = tid & 31;

    // P1 partition: (16 j-chunks of 128 n'-cols) x (16 k-slices of 64)
    const int nc = bid >> 4, ksl = bid & 15;
    const int n0 = nc * 128, k0g = ksl * 64;
    const int c_l = lane & 7, bgrp = lane >> 3;      // 8 col-subs x 4 batch-groups
    const int col0 = n0 + wrp * 16 + c_l * 2;        // warp = colgrp (n'-index)
    // P2 partition: (16 batch-pairs) x (16 j-slices of 32)
    const int bq2 = bid >> 4, ks2 = bid & 15;
    const int b02 = bq2 * 2, j0 = ks2 * 32;
    // P3/P4 partition: batch x 8 m-chunks of 256 rows
    const int ab = bid >> 3, mq = bid & 7;
    const int m0 = mq * 256;
    const int hq = lane & 7, msub = lane >> 3;

    for (int t = 0; t < T_; ++t) {
        // ================= P1: gates GEMM (16 k-slice partials, gate-interleaved cols) =====
        {
            // build v pair tile vp[k][p] = {v(2p), v(2p+1)} : 64k x 16 pairs
            #pragma unroll
            for (int e = 0; e < 4; ++e) {
                int idx = e * 256 + tid;
                int kk = idx & 63, p = idx >> 6;
                int gk = k0g + kk;
                int bb = p * 2;
                float v0, v1;
                if (gk < 256) {
                    v0 = __ldg(&x[(bb * T_ + t) * I_ + gk]);
                    v1 = __ldg(&x[((bb+1) * T_ + t) * I_ + gk]);
                } else if (gk < 512) {
                    if (t == 0) { v0 = 0.f; v1 = 0.f; }
                    else {
                        int r = gk - 256;
                        v0 = 0.f; v1 = 0.f;
                        #pragma unroll
                        for (int mc = 0; mc < 8; ++mc) {
                            v0 += __ldcg(&g_read_part[t-1][mc][bb][r]);
                            v1 += __ldcg(&g_read_part[t-1][mc][bb+1][r]);
                        }
                    }
                } else {
                    v0 = __ldcg(&g_h[bb * H_ + (gk - 512)]);
                    v1 = __ldcg(&g_h[(bb+1) * H_ + (gk - 512)]);
                }
                sm.g.vp[kk][p] = pack2(v0, v1);
            }
            __syncthreads();
            u64 acc[2][4];
            {
                u64 b0p = 0ull, b1p = 0ull;
                if (ksl == 0) {
                    int r0 = (col0 & 3) * 512 + (col0 >> 2);
                    int r1 = ((col0+1) & 3) * 512 + ((col0+1) >> 2);
                    float bi0 = __ldg(&b_ih[r0]) + __ldg(&b_hh[r0]);
                    float bi1 = __ldg(&b_ih[r1]) + __ldg(&b_hh[r1]);
                    b0p = pack2(bi0, bi0); b1p = pack2(bi1, bi1);
                }
                #pragma unroll
                for (int p = 0; p < 4; ++p) { acc[0][p] = b0p; acc[1][p] = b1p; }
            }
            const float2* wp2 = (const float2*)&g_WgT[(size_t)k0g * NG_ + col0];
            const int p0 = bgrp * 4;
            #pragma unroll 8
            for (int kk = 0; kk < 64; ++kk) {
                float2 w = __ldg(wp2 + (size_t)kk * (NG_/2));
                u64 w20 = pack2(w.x, w.x);
                u64 w21 = pack2(w.y, w.y);
                ulonglong2 va = *(const ulonglong2*)&sm.g.vp[kk][p0];
                ulonglong2 vb = *(const ulonglong2*)&sm.g.vp[kk][p0 + 2];
                acc[0][0] = ffma2(va.x, w20, acc[0][0]);
                acc[0][1] = ffma2(va.y, w20, acc[0][1]);
                acc[0][2] = ffma2(vb.x, w20, acc[0][2]);
                acc[0][3] = ffma2(vb.y, w20, acc[0][3]);
                acc[1][0] = ffma2(va.x, w21, acc[1][0]);
                acc[1][1] = ffma2(va.y, w21, acc[1][1]);
                acc[1][2] = ffma2(vb.x, w21, acc[1][2]);
                acc[1][3] = ffma2(vb.y, w21, acc[1][3]);
            }
            #pragma unroll
            for (int p = 0; p < 4; ++p) {
                float2 c0 = unpack2(acc[0][p]);
                float2 c1 = unpack2(acc[1][p]);
                int b = bgrp * 8 + p * 2;
                *(float2*)&g_gates_part[ksl][b][col0]     = make_float2(c0.x, c1.x);
                *(float2*)&g_gates_part[ksl][b + 1][col0] = make_float2(c0.y, c1.y);
            }
            __syncthreads();
        }
        barwait(&g_bar[2*t + 0], NBLK);         // global: P1 -> P2

        // ================= P2: LSTM (quad-spread, vectorized gate loads) + head GEMM =======
        {
            {
                const int cell = tid >> 2, q = tid & 3;     // 64 cells: 2 b x 32 j
                const int bi = cell >> 5, jj = cell & 31;
                const int b = b02 + bi, j = j0 + jj;
                float4 gs = make_float4(0.f, 0.f, 0.f, 0.f);
                #pragma unroll
                for (int e = 0; e < 4; ++e) {
                    int s = q * 4 + e;
                    float4 ga = __ldcg((const float4*)&g_gates_part[s][b][j * 4]);
                    gs.x += ga.x; gs.y += ga.y; gs.z += ga.z; gs.w += ga.w;
                }
                gs.x += __shfl_xor_sync(0xffffffffu, gs.x, 1);
                gs.y += __shfl_xor_sync(0xffffffffu, gs.y, 1);
                gs.z += __shfl_xor_sync(0xffffffffu, gs.z, 1);
                gs.w += __shfl_xor_sync(0xffffffffu, gs.w, 1);
                gs.x += __shfl_xor_sync(0xffffffffu, gs.x, 2);
                gs.y += __shfl_xor_sync(0xffffffffu, gs.y, 2);
                gs.z += __shfl_xor_sync(0xffffffffu, gs.z, 2);
                gs.w += __shfl_xor_sync(0xffffffffu, gs.w, 2);
                if (q == 0) {
                    float cold = g_c[b * H_ + j];
                    float iv = sigm_f(gs.x), fv = sigm_f(gs.y);
                    float gv = tanh_f(gs.z), ov = sigm_f(gs.w);
                    float cn = fv * cold + iv * gv;
                    float hn = ov * tanh_f(cn);
                    g_c[b * H_ + j] = cn;
                    g_h[b * H_ + j] = hn;
                    g_hist_h[t][b][j] = hn;
                    sm.p2.h[bi][jj] = hn;
                }
            }
            __syncthreads();
            #pragma unroll
            for (int e = 0; e < 3; ++e) {
                int nn = tid + e * 256;
                if (nn < NHP_) {
                    float a0 = 0.f, a1 = 0.f;
                    #pragma unroll
                    for (int k = 0; k < 32; ++k) {
                        float w = __ldcg(&g_WhT[(size_t)(j0 + k) * NHP_ + nn]);
                        a0 += sm.p2.h[0][k] * w;
                        a1 += sm.p2.h[1][k] * w;
                    }
                    g_hp_part[ks2][b02 + 0][nn] = a0;
                    g_hp_part[ks2][b02 + 1][nn] = a1;
                }
            }
        }
        // hoist block-private mem-row loads above the barrier (coalesced)
        ulonglong2 rows2[8][2];
        #pragma unroll
        for (int it = 0; it < 8; ++it) {
            const float* mp = &g_mem[ab][m0 + it*32 + wrp*4 + msub][0];
            rows2[it][0] = *(const ulonglong2*)(mp + hq * 4);
            rows2[it][1] = *(const ulonglong2*)(mp + 32 + hq * 4);
        }
        barwait(&g_barG[t][bid >> 4], 16);      // 16-group: P2 -> P3 (hp_part local)

        // ================= P3: keys + ws + scores + sk + chunk stats =================
        {
            #pragma unroll
            for (int e = 0; e < 2; ++e) {       // key build: 512 entries, 2 per thread
                int idx = e * 256 + tid;
                int key = idx >> 6, h = idx & 63;
                int n = key & 3;
                int p = (key < 4) ? h : 64 + h;
                float v = __ldg(&b_head[n * HPROW_ + p]);
                #pragma unroll
                for (int ps = 0; ps < 16; ++ps) v += __ldcg(&g_hp_part[ps][ab][n * 129 + p]);
                sm.a.key[key][h] = v * 0.125f;
            }
            if (tid < 4) {
                int nw = tid;
                float vw = __ldg(&b_head[nw * HPROW_ + 128]);
                #pragma unroll
                for (int ps = 0; ps < 16; ++ps) vw += __ldcg(&g_hp_part[ps][ab][nw * 129 + 128]);
                sm.a.ws[nw] = sigm_f(vw);
            }
            __syncthreads();
            // scores: 2 passes of 4 keys, keys register-hoisted out of the it-loop
            #pragma unroll
            for (int kp = 0; kp < 2; ++kp) {
                const int kb = kp * 4;
                ulonglong2 klo[4], khi[4];
                #pragma unroll
                for (int kq = 0; kq < 4; ++kq) {
                    klo[kq] = *(const ulonglong2*)&sm.a.key[kb + kq][hq * 4];
                    khi[kq] = *(const ulonglong2*)&sm.a.key[kb + kq][32 + hq * 4];
                }
                #pragma unroll
                for (int it = 0; it < 8; ++it) {
                    float pv[4];
                    #pragma unroll
                    for (int kq = 0; kq < 4; ++kq) {
                        u64 d2 = ffma2(rows2[it][0].x, klo[kq].x, 0ull);
                        d2 = ffma2(rows2[it][0].y, klo[kq].y, d2);
                        d2 = ffma2(rows2[it][1].x, khi[kq].x, d2);
                        d2 = ffma2(rows2[it][1].y, khi[kq].y, d2);
                        float2 pf = unpack2(d2);
                        pv[kq] = pf.x + pf.y;
                    }
                    // butterfly over hq: xor1/xor2 key-splits, xor4 plain add
                    float q2v[2];
                    #pragma unroll
                    for (int k2 = 0; k2 < 2; ++k2) {
                        float send = (hq & 1) ? pv[2*k2] : pv[2*k2+1];
                        float recv = __shfl_xor_sync(0xffffffffu, send, 1);
                        float keepv = (hq & 1) ? pv[2*k2+1] : pv[2*k2];
                        q2v[k2] = keepv + recv;
                    }
                    float r1;
                    {
                        float send = (hq & 2) ? q2v[0] : q2v[1];
                        float recv = __shfl_xor_sync(0xffffffffu, send, 2);
                        float keepv = (hq & 2) ? q2v[1] : q2v[0];
                        r1 = keepv + recv;
                    }
                    r1 += __shfl_xor_sync(0xffffffffu, r1, 4);
                    if (hq < 4) sm.a.sc[kb + hq][it*32 + wrp*4 + msub] = r1;
                }
            }
            // sk build (needs ws + hp_part; independent of sc stats below)
            {
                int n = tid >> 6, h = tid & 63;
                float v = __ldg(&b_head[n * HPROW_ + 64 + h]);
                #pragma unroll
                for (int ps = 0; ps < 16; ++ps) v += __ldcg(&g_hp_part[ps][ab][n * 129 + 64 + h]);
                sm.a.sk[n][h] = v * sm.a.ws[n];
            }
            __syncthreads();
            if (wrp < 8) {      // chunk max per key (8 warps = 8 keys)
                float mx = -1e30f;
                for (int i = lane; i < 256; i += 32) mx = fmaxf(mx, sm.a.sc[wrp][i]);
                #pragma unroll
                for (int sh = 16; sh; sh >>= 1) mx = fmaxf(mx, __shfl_xor_sync(0xffffffffu, mx, sh));
                if (lane == 0) sm.a.gm[wrp] = mx;
            }
            __syncthreads();
            #pragma unroll
            for (int key = 0; key < 8; ++key)     // exp in place
                sm.a.sc[key][tid] = __expf(sm.a.sc[key][tid] - sm.a.gm[key]);
            __syncthreads();
            if (wrp < 8) {      // chunk sumexp
                float se = 0.f;
                for (int i = lane; i < 256; i += 32) se += sm.a.sc[wrp][i];
                #pragma unroll
                for (int sh = 16; sh; sh >>= 1) se += __shfl_xor_sync(0xffffffffu, se, sh);
                if (lane == 0) g_stats[ab][wrp][mq] = make_float2(sm.a.gm[wrp], se);
            }
        }
        barwait(&g_barG[t][16 + (bid >> 3)], 8); // 8-group: P3 -> P4 (stats local)

        // ================= P4: softmax apply on register rows, read acc, mem update ==========
        {
            if (tid < 8) {
                float gm = -1e30f;
                float2 st[8];
                #pragma unroll
                for (int c = 0; c < 8; ++c) {
                    st[c] = __ldcg(&g_stats[ab][tid][c]);
                    gm = fmaxf(gm, st[c].x);
                }
                float ssum = 0.f;
                #pragma unroll
                for (int c = 0; c < 8; ++c) ssum += st[c].y * __expf(st[c].x - gm);
                sm.a.inv[tid] = __expf(sm.a.gm[tid] - gm) / ssum;
            }
            __syncthreads();
            float scl[8];
            #pragma unroll
            for (int key = 0; key < 8; ++key) scl[key] = sm.a.inv[key];

            u64 racc2[4][4];
            #pragma unroll
            for (int n = 0; n < 4; ++n)
                #pragma unroll
                for (int q2 = 0; q2 < 4; ++q2) racc2[n][q2] = 0ull;

            #pragma unroll
            for (int it = 0; it < 8; ++it) {
                const int ml = it*32 + wrp*4 + msub;
                float wv[8];
                #pragma unroll
                for (int n = 0; n < 8; ++n) wv[n] = sm.a.sc[n][ml] * scl[n];
                ulonglong2 rlo = rows2[it][0], rhi = rows2[it][1];
                #pragma unroll
                for (int n = 0; n < 4; ++n) {
                    u64 rw2 = pack2(wv[n], wv[n]);
                    racc2[n][0] = ffma2(rw2, rlo.x, racc2[n][0]);
                    racc2[n][1] = ffma2(rw2, rlo.y, racc2[n][1]);
                    racc2[n][2] = ffma2(rw2, rhi.x, racc2[n][2]);
                    racc2[n][3] = ffma2(rw2, rhi.y, racc2[n][3]);
                }
                #pragma unroll
                for (int n = 0; n < 4; ++n) {
                    u64 ww2 = pack2(wv[4 + n], wv[4 + n]);
                    ulonglong2 slo = *(const ulonglong2*)&sm.a.sk[n][hq * 4];
                    ulonglong2 shi = *(const ulonglong2*)&sm.a.sk[n][32 + hq * 4];
                    rlo.x = ffma2(ww2, slo.x, rlo.x);
                    rlo.y = ffma2(ww2, slo.y, rlo.y);
                    rhi.x = ffma2(ww2, shi.x, rhi.x);
                    rhi.y = ffma2(ww2, shi.y, rhi.y);
                }
                float* mp = &g_mem[ab][m0 + ml][0];
                *(ulonglong2*)(mp + hq * 4) = rlo;
                *(ulonglong2*)(mp + 32 + hq * 4) = rhi;
            }
            // reduce read partials over msub (xor 8, 16)
            #pragma unroll
            for (int n = 0; n < 4; ++n)
                #pragma unroll
                for (int q2 = 0; q2 < 4; ++q2) {
                    racc2[n][q2] = fadd2(racc2[n][q2], __shfl_xor_sync(0xffffffffu, racc2[n][q2], 8));
                    racc2[n][q2] = fadd2(racc2[n][q2], __shfl_xor_sync(0xffffffffu, racc2[n][q2], 16));
                }
            if (lane < 8) {   // msub == 0, hq == lane
                #pragma unroll
                for (int n = 0; n < 4; ++n) {
                    float2 p0 = unpack2(racc2[n][0]);
                    float2 p1 = unpack2(racc2[n][1]);
                    float2 p2 = unpack2(racc2[n][2]);
                    float2 p3 = unpack2(racc2[n][3]);
                    *(float2*)&sm.a.racc[wrp][n][hq*4]          = p0;
                    *(float2*)&sm.a.racc[wrp][n][hq*4 + 2]      = p1;
                    *(float2*)&sm.a.racc[wrp][n][32 + hq*4]     = p2;
                    *(float2*)&sm.a.racc[wrp][n][32 + hq*4 + 2] = p3;
                }
            }
            __syncthreads();
            {
                int n = tid >> 6, h = tid & 63;
                float ssum = 0.f;
                #pragma unroll
                for (int wr = 0; wr < 8; ++wr) ssum += sm.a.racc[wr][n][h];
                g_read_part[t][mq][ab][n * 64 + h] = ssum;
            }
        }
        barwait(&g_bar[2*t + 1], NBLK);         // global: P4 -> next P1
    }
}

// ---------------- final output GEMM: outputs[b][t][o] ----------------
__global__ void k_out(const float* __restrict__ b_out, float* __restrict__ out) {
    const int m0 = blockIdx.x * 32, nc = blockIdx.y;
    const int tid = threadIdx.x;
    __shared__ float a_sh[32][64];
    const int n_l = tid & 63, mg = tid >> 6;
    const int n = nc * 64 + n_l;
    float acc[8];
    #pragma unroll
    for (int r = 0; r < 8; ++r) acc[r] = 0.f;
    for (int kt = 0; kt < 12; ++kt) {
        __syncthreads();
        #pragma unroll
        for (int e = 0; e < 8; ++e) {
            int lidx = e * 256 + tid;
            int mrow = lidx >> 6, kk = lidx & 63;
            int m = m0 + mrow;
            int ts = m >> 5, bb = m & 31;
            int gk = kt * 64 + kk;
            float v;
            if (gk < 512) v = g_hist_h[ts][bb][gk];
            else {
                int r = gk - 512;
                v = 0.f;
                #pragma unroll
                for (int mc = 0; mc < 8; ++mc) v += g_read_part[ts][mc][bb][r];
            }
            a_sh[mrow][kk] = v;
        }
        __syncthreads();
        #pragma unroll 4
        for (int kk = 0; kk < 64; ++kk) {
            float wv = g_WoT[(kt * 64 + kk) * O_ + n];
            #pragma unroll
            for (int r = 0; r < 8; ++r) acc[r] += a_sh[mg * 8 + r][kk] * wv;
        }
    }
    float bo = b_out[n];
    #pragma unroll
    for (int r = 0; r < 8; ++r) {
        int m = m0 + mg * 8 + r;
        int ts = m >> 5, bb = m & 31;
        out[(bb * T_ + ts) * O_ + n] = acc[r] + bo;
    }
}

// ---------------- final state copy: mem, h, c into d_out ----------------
__global__ void k_final(float* __restrict__ out) {
    const int OUT_N = B_ * T_ * O_;
    const int NMEM  = B_ * MS_ * HS_;
    const int total = NMEM + 2 * B_ * H_;
    for (int i = blockIdx.x * blockDim.x + threadIdx.x; i < total; i += gridDim.x * blockDim.x) {
        if (i < NMEM)                 out[OUT_N + i] = (&g_mem[0][0][0])[i];
        else if (i < NMEM + B_ * H_)  out[OUT_N + i] = g_h[i - NMEM];
        else                          out[OUT_N + i] = g_c[i - NMEM - B_ * H_];
    }
}

extern "C" void kernel_launch(void* const* d_in, const int* in_sizes, int n_in,
                              void* d_out, int out_size) {
    const float* x      = (const float*)d_in[0];
    const float* W_ih   = (const float*)d_in[1];
    const float* W_hh   = (const float*)d_in[2];
    const float* b_ih   = (const float*)d_in[3];
    const float* b_hh   = (const float*)d_in[4];
    const float* W_head = (const float*)d_in[5];
    const float* b_head = (const float*)d_in[6];
    const float* W_out  = (const float*)d_in[7];
    const float* b_out  = (const float*)d_in[8];
    float* out = (float*)d_out;

    k_prep<<<3024, 256>>>(W_ih, W_hh, W_head, W_out);
    k_nop<<<1, 32>>>();
    k_nop<<<1, 32>>>();
    k_steps<<<NBLK, NTHR>>>(x, b_ih, b_hh, b_head);
    k_out<<<dim3(32, 4), 256>>>(b_out, out);
    k_final<<<2048, 256>>>(out);
}